// round 2
// baseline (speedup 1.0000x reference)
#include <cuda_runtime.h>

// state: (2,)^24 + (4,) float32, row-major. qubit q axis stride = 2^(23-q)*4 elems.
// TARGETS = (5, 12): stride_q5 = 2^18 float4; stride_q12 = 2^11 float4.
// out[a,b] = sum_{i,j} P[(a*2+b)*4 + (i*2+j)] * s[i@q5, j@q12]   (batch in float4 lanes)

#define S12_V (1u << 11)
#define S5_V  (1u << 18)

__global__ void __launch_bounds__(256) gate2q_kernel(
    const float4* __restrict__ state,
    const float*  __restrict__ pauli,
    float4*       __restrict__ out)
{
    unsigned t = blockIdx.x * blockDim.x + threadIdx.x;   // t in [0, 2^21), 2 rest-idx each

    // Two consecutive rest-indices: r = 2t and 2t+1 (both land in bits 0..10
    // region since bit 0 of the rest-index maps to bit 0 of idx).
    unsigned r0 = t << 1;
    unsigned idx = (r0 & 0x7FFu)
                 | (((r0 >> 11) & 0x3Fu) << 12)
                 | ((r0 >> 17) << 19);
    // r0 is even, so idx+1 is the insertion of r0+1 (bit 0 region never carries
    // out: bits 0..10 of r0 end in 0, +1 only touches bit 0).

    // Front-batch all 8 loads (streaming: no reuse).
    float4 a00 = __ldcs(state + idx);
    float4 b00 = __ldcs(state + idx + 1);
    float4 a01 = __ldcs(state + idx + S12_V);
    float4 b01 = __ldcs(state + idx + S12_V + 1);
    float4 a10 = __ldcs(state + idx + S5_V);
    float4 b10 = __ldcs(state + idx + S5_V + 1);
    float4 a11 = __ldcs(state + idx + S5_V + S12_V);
    float4 b11 = __ldcs(state + idx + S5_V + S12_V + 1);

    float p[16];
#pragma unroll
    for (int i = 0; i < 16; ++i) p[i] = __ldg(pauli + i);

#pragma unroll
    for (int r = 0; r < 4; ++r) {
        float pa = p[r * 4 + 0], pb = p[r * 4 + 1], pc = p[r * 4 + 2], pd = p[r * 4 + 3];
        unsigned dst = idx + (r >> 1) * S5_V + (r & 1) * S12_V;

        float4 o;
        o.x = fmaf(pa, a00.x, fmaf(pb, a01.x, fmaf(pc, a10.x, pd * a11.x)));
        o.y = fmaf(pa, a00.y, fmaf(pb, a01.y, fmaf(pc, a10.y, pd * a11.y)));
        o.z = fmaf(pa, a00.z, fmaf(pb, a01.z, fmaf(pc, a10.z, pd * a11.z)));
        o.w = fmaf(pa, a00.w, fmaf(pb, a01.w, fmaf(pc, a10.w, pd * a11.w)));
        __stcs(out + dst, o);

        float4 q;
        q.x = fmaf(pa, b00.x, fmaf(pb, b01.x, fmaf(pc, b10.x, pd * b11.x)));
        q.y = fmaf(pa, b00.y, fmaf(pb, b01.y, fmaf(pc, b10.y, pd * b11.y)));
        q.z = fmaf(pa, b00.z, fmaf(pb, b01.z, fmaf(pc, b10.z, pd * b11.z)));
        q.w = fmaf(pa, b00.w, fmaf(pb, b01.w, fmaf(pc, b10.w, pd * b11.w)));
        __stcs(out + dst + 1, q);
    }
}

extern "C" void kernel_launch(void* const* d_in, const int* in_sizes, int n_in,
                              void* d_out, int out_size)
{
    const float4* state = (const float4*)d_in[0];
    const float*  pauli = (const float*)d_in[1];
    float4*       out   = (float4*)d_out;

    const unsigned n_threads = 1u << 21;   // 2 rest-indices per thread
    gate2q_kernel<<<n_threads / 256, 256>>>(state, pauli, out);
}

// round 3
// speedup vs baseline: 1.0835x; 1.0835x over previous
#include <cuda_runtime.h>

// state: (2,)^24 + (4,) float32, row-major. qubit q axis stride = 2^(23-q)*4 elems.
// TARGETS = (5, 12): stride_q5 = 2^18 float4; stride_q12 = 2^11 float4.
// out[a,b] = sum_{i,j} P[(a*2+b)*4 + (i*2+j)] * s[i@q5, j@q12]   (batch in float4 lanes)

#define S12_V (1u << 11)   // qubit-12 stride in float4 units
#define S5_V  (1u << 18)   // qubit-5  stride in float4 units

__global__ void __launch_bounds__(256) gate2q_kernel(
    const float4* __restrict__ state,
    const float*  __restrict__ pauli,
    float4*       __restrict__ out)
{
    unsigned t = blockIdx.x * blockDim.x + threadIdx.x;   // t in [0, 2^22)

    // Insert zero bits at positions 11 and 18 of the float4 index.
    unsigned idx = (t & 0x7FFu)                    // bits 0..10
                 | (((t >> 11) & 0x3Fu) << 12)     // 6 bits -> 12..17
                 | ((t >> 17) << 19);              // 5 bits -> 19..23

    // Load the 4 coupled amplitudes (streaming — no reuse anywhere).
    float4 s00 = __ldcs(state + idx);                 // q5=0, q12=0
    float4 s01 = __ldcs(state + idx + S12_V);         // q5=0, q12=1
    float4 s10 = __ldcs(state + idx + S5_V);          // q5=1, q12=0
    float4 s11 = __ldcs(state + idx + S5_V + S12_V);  // q5=1, q12=1

    float p[16];
#pragma unroll
    for (int i = 0; i < 16; ++i) p[i] = __ldg(pauli + i);

#pragma unroll
    for (int r = 0; r < 4; ++r) {
        float a = p[r * 4 + 0], b = p[r * 4 + 1], c = p[r * 4 + 2], d = p[r * 4 + 3];
        float4 o;
        o.x = fmaf(a, s00.x, fmaf(b, s01.x, fmaf(c, s10.x, d * s11.x)));
        o.y = fmaf(a, s00.y, fmaf(b, s01.y, fmaf(c, s10.y, d * s11.y)));
        o.z = fmaf(a, s00.z, fmaf(b, s01.z, fmaf(c, s10.z, d * s11.z)));
        o.w = fmaf(a, s00.w, fmaf(b, s01.w, fmaf(c, s10.w, d * s11.w)));
        unsigned dst = idx + (r >> 1) * S5_V + (r & 1) * S12_V;
        __stcs(out + dst, o);
    }
}

extern "C" void kernel_launch(void* const* d_in, const int* in_sizes, int n_in,
                              void* d_out, int out_size)
{
    const float4* state = (const float4*)d_in[0];   // 2^26 floats = 2^24 float4
    const float*  pauli = (const float*)d_in[1];    // 16 floats
    float4*       out   = (float4*)d_out;

    const unsigned n_threads = 1u << 22;            // one per rest-index
    gate2q_kernel<<<n_threads / 256, 256>>>(state, pauli, out);
}